// round 14
// baseline (speedup 1.0000x reference)
#include <cuda_runtime.h>
#include <cuda_fp16.h>
#include <cstdint>

// ---------------------------------------------------------------------------
//   x:[64,1024,512] fp32, w_qkv:[512,1536], w_proj:[512,512], b_proj:[512]
//   out:[64,1024,512]. Token n = h*64+w on 16x64 grid, window |dh|<=3,|dw|<=5.
//   Harness ptxas targets sm_103 (no 'a') -> tcgen05 unavailable.
//   fp16 pipeline (same 10+1-bit mantissa as tf32; fp32 accumulation).
//   R14 = R13 baseline + attn K/V double-buffer (clean re-test of R12 theory;
//   R12's run showed unchanged GEMM1 slowed 78% -> throttled-run confound).
// ---------------------------------------------------------------------------

#define NTOK   1024
#define BATCH  64
#define MTOT   (BATCH * NTOK)      // 65536
#define DIMSZ  512
#define QKVC   1536

static __device__ __half g_xh[(size_t)MTOT * DIMSZ];
static __device__ __half g_qkv[(size_t)MTOT * QKVC];
static __device__ __half g_att[(size_t)MTOT * DIMSZ];
static __device__ __half g_wqkvT[QKVC * DIMSZ];
static __device__ __half g_wprojT[DIMSZ * DIMSZ];

// ---------------------------------------------------------------------------
__device__ __forceinline__ void mma16(float* c, const uint32_t* a,
                                      uint32_t b0, uint32_t b1) {
    asm volatile(
        "mma.sync.aligned.m16n8k16.row.col.f32.f16.f16.f32 "
        "{%0,%1,%2,%3}, {%4,%5,%6,%7}, {%8,%9}, {%0,%1,%2,%3};"
        : "+f"(c[0]), "+f"(c[1]), "+f"(c[2]), "+f"(c[3])
        : "r"(a[0]), "r"(a[1]), "r"(a[2]), "r"(a[3]), "r"(b0), "r"(b1));
}
__device__ __forceinline__ void ldsm4(uint32_t addr, uint32_t* r) {
    asm volatile("ldmatrix.sync.aligned.m8n8.x4.shared.b16 {%0,%1,%2,%3}, [%4];"
                 : "=r"(r[0]), "=r"(r[1]), "=r"(r[2]), "=r"(r[3]) : "r"(addr));
}
__device__ __forceinline__ void ldsm4t(uint32_t addr, uint32_t* r) {
    asm volatile("ldmatrix.sync.aligned.m8n8.x4.trans.shared.b16 {%0,%1,%2,%3}, [%4];"
                 : "=r"(r[0]), "=r"(r[1]), "=r"(r[2]), "=r"(r[3]) : "r"(addr));
}
__device__ __forceinline__ void cpa16(uint32_t dst, const void* src) {
    asm volatile("cp.async.cg.shared.global [%0], [%1], 16;" :: "r"(dst), "l"(src));
}
__device__ __forceinline__ void cpa_commit() { asm volatile("cp.async.commit_group;"); }
template <int N>
__device__ __forceinline__ void cpa_wait() {
    asm volatile("cp.async.wait_group %0;" :: "n"(N));
}
__device__ __forceinline__ uint32_t packh2(float a, float b) {
    __half2 h = __floats2half2_rn(a, b);
    return *reinterpret_cast<uint32_t*>(&h);
}

// ---------------------------------------------------------------------------
// Pre-pass 1: x fp32 -> fp16
// ---------------------------------------------------------------------------
__global__ void cvt_f16_kernel(const float* __restrict__ in,
                               __half* __restrict__ out, int n4) {
    int i = blockIdx.x * blockDim.x + threadIdx.x;
    if (i < n4) {
        float4 v = reinterpret_cast<const float4*>(in)[i];
        __half2 h0 = __floats2half2_rn(v.x, v.y);
        __half2 h1 = __floats2half2_rn(v.z, v.w);
        reinterpret_cast<__half2*>(out)[2 * i]     = h0;
        reinterpret_cast<__half2*>(out)[2 * i + 1] = h1;
    }
}

// ---------------------------------------------------------------------------
// Pre-pass 2: WT[C][R] = fp16(W[R][C])
// ---------------------------------------------------------------------------
__global__ void transpose_cvt_kernel(const float* __restrict__ W,
                                     __half* __restrict__ WT, int R, int C) {
    __shared__ float t[32][33];
    int c0 = blockIdx.x * 32, r0 = blockIdx.y * 32;
    int x = threadIdx.x, y = threadIdx.y;   // block (32, 8)
    #pragma unroll
    for (int i = 0; i < 32; i += 8)
        t[y + i][x] = W[(size_t)(r0 + y + i) * C + c0 + x];
    __syncthreads();
    #pragma unroll
    for (int i = 0; i < 32; i += 8)
        WT[(size_t)(c0 + y + i) * R + r0 + x] = __float2half(t[x][y + i]);
}

// ---------------------------------------------------------------------------
// fp16 GEMM (R9/R13 best config — UNCHANGED): C[M,N] = A[M,K] * BT[N,K].
// Block 128x128, BK=64, 256 thr, 8 warps (2m x 4n), warp tile 64x32.
// 2-stage cp.async + ldmatrix.b16. smem row stride 144B.
// ---------------------------------------------------------------------------
template <bool OUT16>
__global__ __launch_bounds__(256) void gemm_kernel(
    const __half* __restrict__ A, const __half* __restrict__ BT,
    const float* __restrict__ bias, void* __restrict__ Cv, int N, int K)
{
    extern __shared__ char smc[];
    const uint32_t TSZ = 128 * 144;

    const int tid  = threadIdx.x;
    const int lane = tid & 31;
    const int warp = tid >> 5;
    const int g    = lane >> 2;
    const int cc   = lane & 3;
    const int wr   = warp >> 2;
    const int wc   = warp & 3;
    const int bm   = blockIdx.y * 128;
    const int bn   = blockIdx.x * 128;

    const uint32_t smb  = (uint32_t)__cvta_generic_to_shared(smc);
    const uint32_t bOff = 2u * TSZ;

    const int ldrow   = tid >> 3;
    const int ldchunk = tid & 7;
    const uint32_t aDst = smb + ldrow * 144 + ldchunk * 16;
    const uint32_t bDst = aDst + bOff;
    const __half* aSrc = A  + (size_t)(bm + ldrow) * K + ldchunk * 8;
    const __half* bSrc = BT + (size_t)(bn + ldrow) * K + ldchunk * 8;

    const int rowpat = (lane & 7) + ((lane >> 3) & 1) * 8;
    const int colpat = (lane >> 4) * 16;
    uint32_t aLd[4], bLd[2];
    #pragma unroll
    for (int mt = 0; mt < 4; mt++)
        aLd[mt] = smb + (wr * 64 + mt * 16 + rowpat) * 144 + colpat;
    #pragma unroll
    for (int np = 0; np < 2; np++)
        bLd[np] = smb + bOff + (wc * 32 + np * 16 + rowpat) * 144 + colpat;

    float acc[4][4][4];
    #pragma unroll
    for (int mt = 0; mt < 4; mt++)
        #pragma unroll
        for (int nt = 0; nt < 4; nt++)
            #pragma unroll
            for (int r = 0; r < 4; r++) acc[mt][nt][r] = 0.f;

    const int NIT = K >> 6;

    auto load_chunk = [&](int c) {
        const uint32_t so = (uint32_t)(c & 1) * TSZ;
        const int ko = c * 64;
        #pragma unroll
        for (int i = 0; i < 4; i++)
            cpa16(aDst + so + i * (32 * 144), aSrc + (size_t)i * 32 * K + ko);
        #pragma unroll
        for (int i = 0; i < 4; i++)
            cpa16(bDst + so + i * (32 * 144), bSrc + (size_t)i * 32 * K + ko);
        cpa_commit();
    };

    load_chunk(0);

    for (int it = 0; it < NIT; ++it) {
        if (it + 1 < NIT) {
            load_chunk(it + 1);
            cpa_wait<1>();
        } else {
            cpa_wait<0>();
        }
        __syncthreads();

        const uint32_t st = (uint32_t)(it & 1) * TSZ;
        #pragma unroll
        for (int kk = 0; kk < 4; kk++) {
            uint32_t af[4][4], bq[2][4];
            #pragma unroll
            for (int mt = 0; mt < 4; mt++) ldsm4(aLd[mt] + st + kk * 32, af[mt]);
            ldsm4(bLd[0] + st + kk * 32, bq[0]);
            ldsm4(bLd[1] + st + kk * 32, bq[1]);
            #pragma unroll
            for (int mt = 0; mt < 4; mt++) {
                mma16(acc[mt][0], af[mt], bq[0][0], bq[0][2]);
                mma16(acc[mt][1], af[mt], bq[0][1], bq[0][3]);
                mma16(acc[mt][2], af[mt], bq[1][0], bq[1][2]);
                mma16(acc[mt][3], af[mt], bq[1][1], bq[1][3]);
            }
        }
        __syncthreads();
    }

    #pragma unroll
    for (int mt = 0; mt < 4; mt++) {
        #pragma unroll
        for (int nt = 0; nt < 4; nt++) {
            int row = bm + wr * 64 + mt * 16 + g;
            int col = bn + wc * 32 + nt * 8 + cc * 2;
            if (OUT16) {
                __half* C = (__half*)Cv;
                *reinterpret_cast<uint32_t*>(&C[(size_t)row * N + col]) =
                    packh2(acc[mt][nt][0], acc[mt][nt][1]);
                *reinterpret_cast<uint32_t*>(&C[(size_t)(row + 8) * N + col]) =
                    packh2(acc[mt][nt][2], acc[mt][nt][3]);
            } else {
                float* C = (float*)Cv;
                float b0 = bias[col], b1 = bias[col + 1];
                float2 v0 = make_float2(acc[mt][nt][0] + b0, acc[mt][nt][1] + b1);
                float2 v1 = make_float2(acc[mt][nt][2] + b0, acc[mt][nt][3] + b1);
                *reinterpret_cast<float2*>(&C[(size_t)row * N + col])       = v0;
                *reinterpret_cast<float2*>(&C[(size_t)(row + 8) * N + col]) = v1;
            }
        }
    }
}

// ---------------------------------------------------------------------------
// Local attention, fp16, double-buffered K/V (hoisted stage addresses).
// One block per (hq, head, b); 4 warps x 16 q-cols; 32-key window per warp.
// smem: Q/P 64x144, K[2] 64x144, V[2] 64x144 = 46080 B.
// ---------------------------------------------------------------------------
__global__ __launch_bounds__(128) void attn_kernel(
    const __half* __restrict__ qkv, __half* __restrict__ attout)
{
    extern __shared__ char smc[];
    const uint32_t smb = (uint32_t)__cvta_generic_to_shared(smc);
    const uint32_t qsB = smb;
    const uint32_t ksB0 = smb + 1 * 64 * 144;
    const uint32_t ksB1 = smb + 2 * 64 * 144;
    const uint32_t vsB0 = smb + 3 * 64 * 144;
    const uint32_t vsB1 = smb + 4 * 64 * 144;

    const int tid  = threadIdx.x;
    const int lane = tid & 31;
    const int warp = tid >> 5;
    const int g    = lane >> 2;
    const int cc   = lane & 3;
    const int hq   = blockIdx.x;
    const int head = blockIdx.y;
    const int b    = blockIdx.z;
    const int qrow = warp * 16;
    const int k0   = (qrow - 8 < 0) ? 0 : (qrow - 8 > 32 ? 32 : qrow - 8);

    const int rowpat = (lane & 7) + ((lane >> 3) & 1) * 8;
    const int colpat = (lane >> 4) * 16;
    const uint32_t pAddr = qsB + (qrow + rowpat) * 144 + colpat;

    // hoisted per-stage fragment addresses
    uint32_t kAddrS[2][2], vBaseS[2];
    #pragma unroll
    for (int np = 0; np < 2; np++) {
        kAddrS[0][np] = ksB0 + (k0 + np * 16 + rowpat) * 144 + colpat;
        kAddrS[1][np] = ksB1 + (k0 + np * 16 + rowpat) * 144 + colpat;
    }
    vBaseS[0] = vsB0 + rowpat * 144 + colpat;
    vBaseS[1] = vsB1 + rowpat * 144 + colpat;

    const int frow   = tid >> 3;    // 0..15
    const int fchunk = tid & 7;

    const __half* kvbase = qkv + (size_t)b * NTOK * QKVC + DIMSZ + head * 64;

    auto load_kv = [&](int kh, int s) {
        const __half* kb = kvbase + (size_t)(kh * 64) * QKVC;
        const __half* vb = kb + DIMSZ;
        const uint32_t ks = s ? ksB1 : ksB0;
        const uint32_t vs = s ? vsB1 : vsB0;
        #pragma unroll
        for (int i = 0; i < 4; i++) {
            int row = frow + i * 16;
            const size_t goff = (size_t)row * QKVC + fchunk * 8;
            cpa16(ks + row * 144 + fchunk * 16, kb + goff);
            cpa16(vs + row * 144 + fchunk * 16, vb + goff);
        }
        cpa_commit();
    };

    const int kh0 = (hq - 3 > 0)  ? hq - 3 : 0;
    const int kh1 = (hq + 3 < 15) ? hq + 3 : 15;

    // ---- Load Q (group 1) + first K/V chunk (group 2) ----
    {
        const __half* qb = qkv + ((size_t)(b * NTOK + hq * 64)) * QKVC + head * 64;
        #pragma unroll
        for (int i = 0; i < 4; i++)
            cpa16(qsB + (frow + i * 16) * 144 + fchunk * 16,
                  qb + (size_t)(frow + i * 16) * QKVC + fchunk * 8);
        cpa_commit();
    }
    load_kv(kh0, 0);
    cpa_wait<1>();          // Q done; chunk0 may still be in flight
    __syncthreads();

    uint32_t qa[4][4];
    const __half2 qs = __float2half2_rn(0.125f);
    #pragma unroll
    for (int kk = 0; kk < 4; kk++) {
        ldsm4(pAddr + kk * 32, qa[kk]);
        #pragma unroll
        for (int r = 0; r < 4; r++) {
            __half2 h = *reinterpret_cast<__half2*>(&qa[kk][r]);
            h = __hmul2(h, qs);
            qa[kk][r] = *reinterpret_cast<uint32_t*>(&h);
        }
    }
    __syncthreads();        // Q buffer free -> P buffer

    float o[8][4];
    #pragma unroll
    for (int nt = 0; nt < 8; nt++)
        #pragma unroll
        for (int r = 0; r < 4; r++) o[nt][r] = 0.f;
    float mrun[2] = {-1e30f, -1e30f};
    float lrun[2] = {0.f, 0.f};

    for (int kh = kh0; kh <= kh1; kh++) {
        const int s = (kh - kh0) & 1;
        if (kh + 1 <= kh1) {
            load_kv(kh + 1, s ^ 1);   // prefetch into other stage
            cpa_wait<1>();            // current chunk complete
        } else {
            cpa_wait<0>();
        }
        __syncthreads();

        // ---- S = Q K^T over 32-key window ----
        float sx[4][4];
        #pragma unroll
        for (int nt = 0; nt < 4; nt++)
            #pragma unroll
            for (int r = 0; r < 4; r++) sx[nt][r] = 0.f;

        #pragma unroll
        for (int kk = 0; kk < 4; kk++) {
            #pragma unroll
            for (int np = 0; np < 2; np++) {
                uint32_t kq[4];
                ldsm4(kAddrS[s][np] + kk * 32, kq);
                mma16(sx[2 * np    ], qa[kk], kq[0], kq[2]);
                mma16(sx[2 * np + 1], qa[kk], kq[1], kq[3]);
            }
        }

        // ---- Mask + online softmax ----
        float mloc[2] = {mrun[0], mrun[1]};
        #pragma unroll
        for (int nt = 0; nt < 4; nt++) {
            #pragma unroll
            for (int r = 0; r < 4; r++) {
                int qw = qrow + g + ((r >> 1) << 3);
                int kw = k0 + nt * 8 + cc * 2 + (r & 1);
                int d  = qw - kw;
                if (d > 5 || d < -5) sx[nt][r] = -1e30f;
                mloc[r >> 1] = fmaxf(mloc[r >> 1], sx[nt][r]);
            }
        }
        #pragma unroll
        for (int h = 0; h < 2; h++) {
            mloc[h] = fmaxf(mloc[h], __shfl_xor_sync(0xffffffffu, mloc[h], 1));
            mloc[h] = fmaxf(mloc[h], __shfl_xor_sync(0xffffffffu, mloc[h], 2));
        }
        float alpha[2];
        #pragma unroll
        for (int h = 0; h < 2; h++) {
            alpha[h] = __expf(mrun[h] - mloc[h]);
            mrun[h]  = mloc[h];
        }
        float rs[2] = {0.f, 0.f};
        #pragma unroll
        for (int nt = 0; nt < 4; nt++) {
            #pragma unroll
            for (int r = 0; r < 4; r++) {
                float p = __expf(sx[nt][r] - mrun[r >> 1]);
                sx[nt][r] = p;
                rs[r >> 1] += p;
            }
        }
        #pragma unroll
        for (int h = 0; h < 2; h++) {
            rs[h] += __shfl_xor_sync(0xffffffffu, rs[h], 1);
            rs[h] += __shfl_xor_sync(0xffffffffu, rs[h], 2);
            lrun[h] = lrun[h] * alpha[h] + rs[h];
        }
        #pragma unroll
        for (int nt = 0; nt < 8; nt++)
            #pragma unroll
            for (int r = 0; r < 4; r++) o[nt][r] *= alpha[r >> 1];

        // ---- P -> fp16 smem (private rows) -> A-frags ----
        #pragma unroll
        for (int nt = 0; nt < 4; nt++) {
            int cb = (nt * 8 + cc * 2) * 2;
            *reinterpret_cast<uint32_t*>(smc + (qrow + g    ) * 144 + cb) =
                packh2(sx[nt][0], sx[nt][1]);
            *reinterpret_cast<uint32_t*>(smc + (qrow + g + 8) * 144 + cb) =
                packh2(sx[nt][2], sx[nt][3]);
        }
        __syncwarp();

        // ---- O += P V : 2 k16 steps, V frags via ldmatrix.trans ----
        #pragma unroll
        for (int kk = 0; kk < 2; kk++) {
            uint32_t pa[4];
            ldsm4(pAddr + kk * 32, pa);
            const uint32_t vrow = vBaseS[s] + (k0 + kk * 16) * 144;
            #pragma unroll
            for (int db = 0; db < 4; db++) {
                uint32_t vq[4];
                ldsm4t(vrow + db * 32, vq);
                mma16(o[2 * db    ], pa, vq[0], vq[1]);
                mma16(o[2 * db + 1], pa, vq[2], vq[3]);
            }
        }
        __syncthreads();   // stage s free for the prefetch two iters ahead
    }

    float inv[2] = {1.f / lrun[0], 1.f / lrun[1]};
    __half* ob = attout + ((size_t)(b * NTOK + hq * 64)) * DIMSZ + head * 64;
    #pragma unroll
    for (int nt = 0; nt < 8; nt++) {
        int col = nt * 8 + cc * 2;
        *reinterpret_cast<uint32_t*>(&ob[(size_t)(qrow + g    ) * DIMSZ + col]) =
            packh2(o[nt][0] * inv[0], o[nt][1] * inv[0]);
        *reinterpret_cast<uint32_t*>(&ob[(size_t)(qrow + g + 8) * DIMSZ + col]) =
            packh2(o[nt][2] * inv[1], o[nt][3] * inv[1]);
    }
}

// ---------------------------------------------------------------------------
extern "C" void kernel_launch(void* const* d_in, const int* in_sizes, int n_in,
                              void* d_out, int out_size)
{
    (void)in_sizes; (void)n_in; (void)out_size;
    const float* x      = (const float*)d_in[0];
    const float* w_qkv  = (const float*)d_in[1];
    const float* w_proj = (const float*)d_in[2];
    const float* b_proj = (const float*)d_in[3];
    float* out = (float*)d_out;

    __half *xh, *qkv_ptr, *att_ptr, *wqkvT, *wprojT;
    cudaGetSymbolAddress((void**)&xh, g_xh);
    cudaGetSymbolAddress((void**)&qkv_ptr, g_qkv);
    cudaGetSymbolAddress((void**)&att_ptr, g_att);
    cudaGetSymbolAddress((void**)&wqkvT, g_wqkvT);
    cudaGetSymbolAddress((void**)&wprojT, g_wprojT);

    const int gemm_smem = 4 * 128 * 144;    // 73728
    const int attn_smem = 5 * 64 * 144;     // 46080
    cudaFuncSetAttribute((const void*)gemm_kernel<true>,
                         cudaFuncAttributeMaxDynamicSharedMemorySize, gemm_smem);
    cudaFuncSetAttribute((const void*)gemm_kernel<false>,
                         cudaFuncAttributeMaxDynamicSharedMemorySize, gemm_smem);
    cudaFuncSetAttribute((const void*)attn_kernel,
                         cudaFuncAttributeMaxDynamicSharedMemorySize, attn_smem);

    // 0) Pre-passes: x -> fp16; weights -> transposed fp16
    const int n4 = MTOT * DIMSZ / 4;
    cvt_f16_kernel<<<(n4 + 255) / 256, 256>>>(x, xh, n4);
    transpose_cvt_kernel<<<dim3(QKVC / 32, DIMSZ / 32), dim3(32, 8)>>>(
        w_qkv, wqkvT, DIMSZ, QKVC);
    transpose_cvt_kernel<<<dim3(DIMSZ / 32, DIMSZ / 32), dim3(32, 8)>>>(
        w_proj, wprojT, DIMSZ, DIMSZ);

    // 1) QKV GEMM (fp16 in/out)
    gemm_kernel<true><<<dim3(QKVC / 128, MTOT / 128), 256, gemm_smem>>>(
        xh, wqkvT, nullptr, qkv_ptr, QKVC, DIMSZ);

    // 2) Local attention (double-buffered K/V)
    attn_kernel<<<dim3(16, 8, BATCH), 128, attn_smem>>>(qkv_ptr, att_ptr);

    // 3) Projection (fp16 in, fp32 out + bias)
    gemm_kernel<false><<<dim3(DIMSZ / 128, MTOT / 128), 256, gemm_smem>>>(
        att_ptr, wprojT, b_proj, out, DIMSZ, DIMSZ);
}

// round 15
// speedup vs baseline: 1.0352x; 1.0352x over previous
#include <cuda_runtime.h>
#include <cuda_fp16.h>
#include <cstdint>

// ---------------------------------------------------------------------------
//   x:[64,1024,512] fp32, w_qkv:[512,1536], w_proj:[512,512], b_proj:[512]
//   out:[64,1024,512]. Token n = h*64+w on 16x64 grid, window |dh|<=3,|dw|<=5.
//   Harness ptxas targets sm_103 (no 'a') -> tcgen05 unavailable.
//   fp16 pipeline (same 10+1-bit mantissa as tf32; fp32 accumulation).
//   R15 = R13 baseline (attn single-buffer) + f16x2 ex2 softmax
//   (attn is MUFU-bound: 18 -> 10 MUFU ops per chunk per thread).
// ---------------------------------------------------------------------------

#define NTOK   1024
#define BATCH  64
#define MTOT   (BATCH * NTOK)      // 65536
#define DIMSZ  512
#define QKVC   1536

static __device__ __half g_xh[(size_t)MTOT * DIMSZ];
static __device__ __half g_qkv[(size_t)MTOT * QKVC];
static __device__ __half g_att[(size_t)MTOT * DIMSZ];
static __device__ __half g_wqkvT[QKVC * DIMSZ];
static __device__ __half g_wprojT[DIMSZ * DIMSZ];

// ---------------------------------------------------------------------------
__device__ __forceinline__ void mma16(float* c, const uint32_t* a,
                                      uint32_t b0, uint32_t b1) {
    asm volatile(
        "mma.sync.aligned.m16n8k16.row.col.f32.f16.f16.f32 "
        "{%0,%1,%2,%3}, {%4,%5,%6,%7}, {%8,%9}, {%0,%1,%2,%3};"
        : "+f"(c[0]), "+f"(c[1]), "+f"(c[2]), "+f"(c[3])
        : "r"(a[0]), "r"(a[1]), "r"(a[2]), "r"(a[3]), "r"(b0), "r"(b1));
}
__device__ __forceinline__ void ldsm4(uint32_t addr, uint32_t* r) {
    asm volatile("ldmatrix.sync.aligned.m8n8.x4.shared.b16 {%0,%1,%2,%3}, [%4];"
                 : "=r"(r[0]), "=r"(r[1]), "=r"(r[2]), "=r"(r[3]) : "r"(addr));
}
__device__ __forceinline__ void ldsm4t(uint32_t addr, uint32_t* r) {
    asm volatile("ldmatrix.sync.aligned.m8n8.x4.trans.shared.b16 {%0,%1,%2,%3}, [%4];"
                 : "=r"(r[0]), "=r"(r[1]), "=r"(r[2]), "=r"(r[3]) : "r"(addr));
}
__device__ __forceinline__ void cpa16(uint32_t dst, const void* src) {
    asm volatile("cp.async.cg.shared.global [%0], [%1], 16;" :: "r"(dst), "l"(src));
}
__device__ __forceinline__ void cpa_commit() { asm volatile("cp.async.commit_group;"); }
template <int N>
__device__ __forceinline__ void cpa_wait() {
    asm volatile("cp.async.wait_group %0;" :: "n"(N));
}
__device__ __forceinline__ uint32_t packh2(float a, float b) {
    __half2 h = __floats2half2_rn(a, b);
    return *reinterpret_cast<uint32_t*>(&h);
}
// 2^x on packed halves (one MUFU op -> two exponentials)
__device__ __forceinline__ uint32_t ex2h2(float a, float b) {
    __half2 h = __floats2half2_rn(a, b);
    uint32_t hin = *reinterpret_cast<uint32_t*>(&h), r;
    asm("ex2.approx.f16x2 %0, %1;" : "=r"(r) : "r"(hin));
    return r;
}

// ---------------------------------------------------------------------------
// Pre-pass 1: x fp32 -> fp16
// ---------------------------------------------------------------------------
__global__ void cvt_f16_kernel(const float* __restrict__ in,
                               __half* __restrict__ out, int n4) {
    int i = blockIdx.x * blockDim.x + threadIdx.x;
    if (i < n4) {
        float4 v = reinterpret_cast<const float4*>(in)[i];
        __half2 h0 = __floats2half2_rn(v.x, v.y);
        __half2 h1 = __floats2half2_rn(v.z, v.w);
        reinterpret_cast<__half2*>(out)[2 * i]     = h0;
        reinterpret_cast<__half2*>(out)[2 * i + 1] = h1;
    }
}

// ---------------------------------------------------------------------------
// Pre-pass 2: WT[C][R] = fp16(W[R][C])
// ---------------------------------------------------------------------------
__global__ void transpose_cvt_kernel(const float* __restrict__ W,
                                     __half* __restrict__ WT, int R, int C) {
    __shared__ float t[32][33];
    int c0 = blockIdx.x * 32, r0 = blockIdx.y * 32;
    int x = threadIdx.x, y = threadIdx.y;   // block (32, 8)
    #pragma unroll
    for (int i = 0; i < 32; i += 8)
        t[y + i][x] = W[(size_t)(r0 + y + i) * C + c0 + x];
    __syncthreads();
    #pragma unroll
    for (int i = 0; i < 32; i += 8)
        WT[(size_t)(c0 + y + i) * R + r0 + x] = __float2half(t[x][y + i]);
}

// ---------------------------------------------------------------------------
// fp16 GEMM (R9/R13 best config — UNCHANGED): C[M,N] = A[M,K] * BT[N,K].
// Block 128x128, BK=64, 256 thr, 8 warps (2m x 4n), warp tile 64x32.
// 2-stage cp.async + ldmatrix.b16. smem row stride 144B.
// ---------------------------------------------------------------------------
template <bool OUT16>
__global__ __launch_bounds__(256) void gemm_kernel(
    const __half* __restrict__ A, const __half* __restrict__ BT,
    const float* __restrict__ bias, void* __restrict__ Cv, int N, int K)
{
    extern __shared__ char smc[];
    const uint32_t TSZ = 128 * 144;

    const int tid  = threadIdx.x;
    const int lane = tid & 31;
    const int warp = tid >> 5;
    const int g    = lane >> 2;
    const int cc   = lane & 3;
    const int wr   = warp >> 2;
    const int wc   = warp & 3;
    const int bm   = blockIdx.y * 128;
    const int bn   = blockIdx.x * 128;

    const uint32_t smb  = (uint32_t)__cvta_generic_to_shared(smc);
    const uint32_t bOff = 2u * TSZ;

    const int ldrow   = tid >> 3;
    const int ldchunk = tid & 7;
    const uint32_t aDst = smb + ldrow * 144 + ldchunk * 16;
    const uint32_t bDst = aDst + bOff;
    const __half* aSrc = A  + (size_t)(bm + ldrow) * K + ldchunk * 8;
    const __half* bSrc = BT + (size_t)(bn + ldrow) * K + ldchunk * 8;

    const int rowpat = (lane & 7) + ((lane >> 3) & 1) * 8;
    const int colpat = (lane >> 4) * 16;
    uint32_t aLd[4], bLd[2];
    #pragma unroll
    for (int mt = 0; mt < 4; mt++)
        aLd[mt] = smb + (wr * 64 + mt * 16 + rowpat) * 144 + colpat;
    #pragma unroll
    for (int np = 0; np < 2; np++)
        bLd[np] = smb + bOff + (wc * 32 + np * 16 + rowpat) * 144 + colpat;

    float acc[4][4][4];
    #pragma unroll
    for (int mt = 0; mt < 4; mt++)
        #pragma unroll
        for (int nt = 0; nt < 4; nt++)
            #pragma unroll
            for (int r = 0; r < 4; r++) acc[mt][nt][r] = 0.f;

    const int NIT = K >> 6;

    auto load_chunk = [&](int c) {
        const uint32_t so = (uint32_t)(c & 1) * TSZ;
        const int ko = c * 64;
        #pragma unroll
        for (int i = 0; i < 4; i++)
            cpa16(aDst + so + i * (32 * 144), aSrc + (size_t)i * 32 * K + ko);
        #pragma unroll
        for (int i = 0; i < 4; i++)
            cpa16(bDst + so + i * (32 * 144), bSrc + (size_t)i * 32 * K + ko);
        cpa_commit();
    };

    load_chunk(0);

    for (int it = 0; it < NIT; ++it) {
        if (it + 1 < NIT) {
            load_chunk(it + 1);
            cpa_wait<1>();
        } else {
            cpa_wait<0>();
        }
        __syncthreads();

        const uint32_t st = (uint32_t)(it & 1) * TSZ;
        #pragma unroll
        for (int kk = 0; kk < 4; kk++) {
            uint32_t af[4][4], bq[2][4];
            #pragma unroll
            for (int mt = 0; mt < 4; mt++) ldsm4(aLd[mt] + st + kk * 32, af[mt]);
            ldsm4(bLd[0] + st + kk * 32, bq[0]);
            ldsm4(bLd[1] + st + kk * 32, bq[1]);
            #pragma unroll
            for (int mt = 0; mt < 4; mt++) {
                mma16(acc[mt][0], af[mt], bq[0][0], bq[0][2]);
                mma16(acc[mt][1], af[mt], bq[0][1], bq[0][3]);
                mma16(acc[mt][2], af[mt], bq[1][0], bq[1][2]);
                mma16(acc[mt][3], af[mt], bq[1][1], bq[1][3]);
            }
        }
        __syncthreads();
    }

    #pragma unroll
    for (int mt = 0; mt < 4; mt++) {
        #pragma unroll
        for (int nt = 0; nt < 4; nt++) {
            int row = bm + wr * 64 + mt * 16 + g;
            int col = bn + wc * 32 + nt * 8 + cc * 2;
            if (OUT16) {
                __half* C = (__half*)Cv;
                *reinterpret_cast<uint32_t*>(&C[(size_t)row * N + col]) =
                    packh2(acc[mt][nt][0], acc[mt][nt][1]);
                *reinterpret_cast<uint32_t*>(&C[(size_t)(row + 8) * N + col]) =
                    packh2(acc[mt][nt][2], acc[mt][nt][3]);
            } else {
                float* C = (float*)Cv;
                float b0 = bias[col], b1 = bias[col + 1];
                float2 v0 = make_float2(acc[mt][nt][0] + b0, acc[mt][nt][1] + b1);
                float2 v1 = make_float2(acc[mt][nt][2] + b0, acc[mt][nt][3] + b1);
                *reinterpret_cast<float2*>(&C[(size_t)row * N + col])       = v0;
                *reinterpret_cast<float2*>(&C[(size_t)(row + 8) * N + col]) = v1;
            }
        }
    }
}

// ---------------------------------------------------------------------------
// Local attention, fp16, single-buffer (R9) + f16x2 ex2 softmax.
// One block per (hq, head, b); 4 warps x 16 q-cols; 32-key window per warp.
// smem: Q/P 64x144B, K 64x144B, V 64x144B = 27648 B.
// ---------------------------------------------------------------------------
__global__ __launch_bounds__(128) void attn_kernel(
    const __half* __restrict__ qkv, __half* __restrict__ attout)
{
    extern __shared__ char smc[];
    const uint32_t smb = (uint32_t)__cvta_generic_to_shared(smc);
    const uint32_t qsB = smb;
    const uint32_t ksB = smb + 64 * 144;
    const uint32_t vsB = smb + 2 * 64 * 144;

    const int tid  = threadIdx.x;
    const int lane = tid & 31;
    const int warp = tid >> 5;
    const int g    = lane >> 2;
    const int cc   = lane & 3;
    const int hq   = blockIdx.x;
    const int head = blockIdx.y;
    const int b    = blockIdx.z;
    const int qrow = warp * 16;
    const int k0   = (qrow - 8 < 0) ? 0 : (qrow - 8 > 32 ? 32 : qrow - 8);

    const int rowpat = (lane & 7) + ((lane >> 3) & 1) * 8;
    const int colpat = (lane >> 4) * 16;
    uint32_t kAddr[2];
    #pragma unroll
    for (int np = 0; np < 2; np++)
        kAddr[np] = ksB + (k0 + np * 16 + rowpat) * 144 + colpat;
    const uint32_t pAddr = qsB + (qrow + rowpat) * 144 + colpat;
    const uint32_t vBase = vsB + rowpat * 144 + colpat;

    const int frow   = tid >> 3;    // 0..15
    const int fchunk = tid & 7;

    // ---- Load Q (fp16) ----
    {
        const __half* qb = qkv + ((size_t)(b * NTOK + hq * 64)) * QKVC + head * 64;
        #pragma unroll
        for (int i = 0; i < 4; i++)
            cpa16(qsB + (frow + i * 16) * 144 + fchunk * 16,
                  qb + (size_t)(frow + i * 16) * QKVC + fchunk * 8);
        cpa_commit();
        cpa_wait<0>();
    }
    __syncthreads();

    uint32_t qa[4][4];
    const __half2 qs = __float2half2_rn(0.125f);
    #pragma unroll
    for (int kk = 0; kk < 4; kk++) {
        ldsm4(pAddr + kk * 32, qa[kk]);
        #pragma unroll
        for (int r = 0; r < 4; r++) {
            __half2 h = *reinterpret_cast<__half2*>(&qa[kk][r]);
            h = __hmul2(h, qs);
            qa[kk][r] = *reinterpret_cast<uint32_t*>(&h);
        }
    }
    __syncthreads();                 // Q buffer free -> P buffer

    float o[8][4];
    #pragma unroll
    for (int nt = 0; nt < 8; nt++)
        #pragma unroll
        for (int r = 0; r < 4; r++) o[nt][r] = 0.f;
    float mrun[2] = {-1e30f, -1e30f};
    float lrun[2] = {0.f, 0.f};

    const int kh0 = (hq - 3 > 0)  ? hq - 3 : 0;
    const int kh1 = (hq + 3 < 15) ? hq + 3 : 15;
    const float L2E = 1.4426950408889634f;

    for (int kh = kh0; kh <= kh1; kh++) {
        const __half* kb = qkv + ((size_t)(b * NTOK + kh * 64)) * QKVC + DIMSZ + head * 64;
        const __half* vb = kb + DIMSZ;
        #pragma unroll
        for (int i = 0; i < 4; i++) {
            int row = frow + i * 16;
            const size_t goff = (size_t)row * QKVC + fchunk * 8;
            cpa16(ksB + row * 144 + fchunk * 16, kb + goff);
            cpa16(vsB + row * 144 + fchunk * 16, vb + goff);
        }
        cpa_commit();
        cpa_wait<0>();
        __syncthreads();

        // ---- S = Q K^T over 32-key window (4 k16 steps over d=64) ----
        float s[4][4];
        #pragma unroll
        for (int nt = 0; nt < 4; nt++)
            #pragma unroll
            for (int r = 0; r < 4; r++) s[nt][r] = 0.f;

        #pragma unroll
        for (int kk = 0; kk < 4; kk++) {
            #pragma unroll
            for (int np = 0; np < 2; np++) {
                uint32_t kq[4];
                ldsm4(kAddr[np] + kk * 32, kq);
                mma16(s[2 * np    ], qa[kk], kq[0], kq[2]);
                mma16(s[2 * np + 1], qa[kk], kq[1], kq[3]);
            }
        }

        // ---- Mask + running max ----
        float mloc[2] = {mrun[0], mrun[1]};
        #pragma unroll
        for (int nt = 0; nt < 4; nt++) {
            #pragma unroll
            for (int r = 0; r < 4; r++) {
                int qw = qrow + g + ((r >> 1) << 3);
                int kw = k0 + nt * 8 + cc * 2 + (r & 1);
                int d  = qw - kw;
                if (d > 5 || d < -5) s[nt][r] = -1e30f;
                mloc[r >> 1] = fmaxf(mloc[r >> 1], s[nt][r]);
            }
        }
        #pragma unroll
        for (int h = 0; h < 2; h++) {
            mloc[h] = fmaxf(mloc[h], __shfl_xor_sync(0xffffffffu, mloc[h], 1));
            mloc[h] = fmaxf(mloc[h], __shfl_xor_sync(0xffffffffu, mloc[h], 2));
        }
        float alpha[2];
        #pragma unroll
        for (int h = 0; h < 2; h++) {
            alpha[h] = __expf(mrun[h] - mloc[h]);
            mrun[h]  = mloc[h];
        }

        // ---- P = 2^((s - m)·log2e) via f16x2 ex2, stored to smem + summed ----
        float rs[2] = {0.f, 0.f};
        #pragma unroll
        for (int nt = 0; nt < 4; nt++) {
            uint32_t p01 = ex2h2((s[nt][0] - mrun[0]) * L2E,
                                 (s[nt][1] - mrun[0]) * L2E);
            uint32_t p23 = ex2h2((s[nt][2] - mrun[1]) * L2E,
                                 (s[nt][3] - mrun[1]) * L2E);
            int cb = (nt * 8 + cc * 2) * 2;   // byte offset in row
            *reinterpret_cast<uint32_t*>(smc + (qrow + g    ) * 144 + cb) = p01;
            *reinterpret_cast<uint32_t*>(smc + (qrow + g + 8) * 144 + cb) = p23;
            float2 f01 = __half22float2(*reinterpret_cast<__half2*>(&p01));
            float2 f23 = __half22float2(*reinterpret_cast<__half2*>(&p23));
            rs[0] += f01.x + f01.y;
            rs[1] += f23.x + f23.y;
        }
        #pragma unroll
        for (int h = 0; h < 2; h++) {
            rs[h] += __shfl_xor_sync(0xffffffffu, rs[h], 1);
            rs[h] += __shfl_xor_sync(0xffffffffu, rs[h], 2);
            lrun[h] = lrun[h] * alpha[h] + rs[h];
        }
        #pragma unroll
        for (int nt = 0; nt < 8; nt++)
            #pragma unroll
            for (int r = 0; r < 4; r++) o[nt][r] *= alpha[r >> 1];
        __syncwarp();

        // ---- O += P V : 2 k16 steps, V frags via ldmatrix.trans ----
        #pragma unroll
        for (int kk = 0; kk < 2; kk++) {
            uint32_t pa[4];
            ldsm4(pAddr + kk * 32, pa);
            const uint32_t vrow = vBase + (k0 + kk * 16) * 144;
            #pragma unroll
            for (int db = 0; db < 4; db++) {
                uint32_t vq[4];
                ldsm4t(vrow + db * 32, vq);
                mma16(o[2 * db    ], pa, vq[0], vq[1]);
                mma16(o[2 * db + 1], pa, vq[2], vq[3]);
            }
        }
        __syncthreads();
    }

    float inv[2] = {1.f / lrun[0], 1.f / lrun[1]};
    __half* ob = attout + ((size_t)(b * NTOK + hq * 64)) * DIMSZ + head * 64;
    #pragma unroll
    for (int nt = 0; nt < 8; nt++) {
        int col = nt * 8 + cc * 2;
        *reinterpret_cast<uint32_t*>(&ob[(size_t)(qrow + g    ) * DIMSZ + col]) =
            packh2(o[nt][0] * inv[0], o[nt][1] * inv[0]);
        *reinterpret_cast<uint32_t*>(&ob[(size_t)(qrow + g + 8) * DIMSZ + col]) =
            packh2(o[nt][2] * inv[1], o[nt][3] * inv[1]);
    }
}

// ---------------------------------------------------------------------------
extern "C" void kernel_launch(void* const* d_in, const int* in_sizes, int n_in,
                              void* d_out, int out_size)
{
    (void)in_sizes; (void)n_in; (void)out_size;
    const float* x      = (const float*)d_in[0];
    const float* w_qkv  = (const float*)d_in[1];
    const float* w_proj = (const float*)d_in[2];
    const float* b_proj = (const float*)d_in[3];
    float* out = (float*)d_out;

    __half *xh, *qkv_ptr, *att_ptr, *wqkvT, *wprojT;
    cudaGetSymbolAddress((void**)&xh, g_xh);
    cudaGetSymbolAddress((void**)&qkv_ptr, g_qkv);
    cudaGetSymbolAddress((void**)&att_ptr, g_att);
    cudaGetSymbolAddress((void**)&wqkvT, g_wqkvT);
    cudaGetSymbolAddress((void**)&wprojT, g_wprojT);

    const int gemm_smem = 4 * 128 * 144;    // 73728
    const int attn_smem = 3 * 64 * 144;     // 27648
    cudaFuncSetAttribute((const void*)gemm_kernel<true>,
                         cudaFuncAttributeMaxDynamicSharedMemorySize, gemm_smem);
    cudaFuncSetAttribute((const void*)gemm_kernel<false>,
                         cudaFuncAttributeMaxDynamicSharedMemorySize, gemm_smem);
    cudaFuncSetAttribute((const void*)attn_kernel,
                         cudaFuncAttributeMaxDynamicSharedMemorySize, attn_smem);

    // 0) Pre-passes: x -> fp16; weights -> transposed fp16
    const int n4 = MTOT * DIMSZ / 4;
    cvt_f16_kernel<<<(n4 + 255) / 256, 256>>>(x, xh, n4);
    transpose_cvt_kernel<<<dim3(QKVC / 32, DIMSZ / 32), dim3(32, 8)>>>(
        w_qkv, wqkvT, DIMSZ, QKVC);
    transpose_cvt_kernel<<<dim3(DIMSZ / 32, DIMSZ / 32), dim3(32, 8)>>>(
        w_proj, wprojT, DIMSZ, DIMSZ);

    // 1) QKV GEMM (fp16 in/out)
    gemm_kernel<true><<<dim3(QKVC / 128, MTOT / 128), 256, gemm_smem>>>(
        xh, wqkvT, nullptr, qkv_ptr, QKVC, DIMSZ);

    // 2) Local attention (fp16 in/out, fp32 softmax stats, f16x2 ex2)
    attn_kernel<<<dim3(16, 8, BATCH), 128, attn_smem>>>(qkv_ptr, att_ptr);

    // 3) Projection (fp16 in, fp32 out + bias)
    gemm_kernel<false><<<dim3(DIMSZ / 128, MTOT / 128), 256, gemm_smem>>>(
        att_ptr, wprojT, b_proj, out, DIMSZ, DIMSZ);
}